// round 13
// baseline (speedup 1.0000x reference)
#include <cuda_runtime.h>

#define KCLS 256
#define WARPS_PER_BLOCK 8
#define THREADS (WARPS_PER_BLOCK * 32)
#define BLOCKS_RESIDENT 444   // 3 blocks/SM * 148 SMs

__device__ __forceinline__ float ex2f(float a) {
    float r; asm("ex2.approx.f32 %0, %1;" : "=f"(r) : "f"(a)); return r;
}
__device__ __forceinline__ float rcpf(float a) {
    float r; asm("rcp.approx.f32 %0, %1;" : "=f"(r) : "f"(a)); return r;
}

// Two-stage software pipeline: row it's front-end (scan+exp) overlaps
// row it-1's epilogue (butterfly+scale+store).
__global__ __launch_bounds__(THREADS, 3)
void dbf_kernel(const int* __restrict__ data,
                const float* __restrict__ t,
                const float4* __restrict__ noise,
                float4* __restrict__ out,
                int nrows)
{
    __shared__ __align__(16) float sg[KCLS];
    __shared__ __align__(16) float sr[KCLS];   // r_k = h_k/g_k = T/(a+T)

    const int tid  = threadIdx.x;
    const int lane = tid & 31;
    const int warp = tid >> 5;

    // Closed-form Cholesky of C0 = (K+0.001) I - 11^T:
    //   T_k = a/(k-a), g_k = sqrt(a+T_k), h_k = T_k/g_k, a = K+0.001
    {
        const float ALPHA = 256.001f;
        float kf = (float)tid;
        float T  = ALPHA / (kf - ALPHA);
        float gs = ALPHA + T;
        sg[tid] = sqrtf(gs);
        sr[tid] = T / gs;          // ratio h/g
    }
    __syncthreads();

    const int kbase = lane * 8;

    float4 ga = *(const float4*)&sg[kbase];
    float4 gb = *(const float4*)&sg[kbase + 4];
    float4 ra = *(const float4*)&sr[kbase];
    float4 rb = *(const float4*)&sr[kbase + 4];
    const float rt[8] = {ra.x, ra.y, ra.z, ra.w, rb.x, rb.y, rb.z, rb.w};

    const float L2E = 1.4426950408889634f;
    const int stride = gridDim.x * WARPS_PER_BLOCK;
    const int gw = blockIdx.x * WARPS_PER_BLOCK + warp;
    if (gw >= nrows) return;

    const int niter = (nrows - gw + stride - 1) / stride;

    const float*  tp = t + gw;
    const int*    dp = data + gw;
    const float4* np = noise + (size_t)gw * (KCLS / 4) + lane * 2;
    float4*       op = out   + (size_t)gw * (KCLS / 4) + lane * 2;
    const size_t  nstep = (size_t)stride * (KCLS / 4);

    // Prime the load pipeline
    float tv = __ldg(tp);
    int   x  = __ldg(dp);
    float4 n0 = __ldg(np + 0);
    float4 n1 = __ldg(np + 1);

    // Deferred-epilogue state (row it-1)
    float  pf[8];
    float  pwq = 0.0f, ps = 0.0f;
    float4* pop = op;

    for (int it = 0; it < niter; it++) {
        // ---- Prefetch next row ----
        const bool hn = (it + 1 < niter);
        float tv_n; int x_n; float4 m0, m1;
        if (hn) {
            tv_n = __ldg(tp + stride);
            x_n  = __ldg(dp + stride);
            m0   = __ldg(np + nstep + 0);
            m1   = __ldg(np + nstep + 1);
        }

        // ---- Front-end of current row ----
        float sb = fminf(tv, 1.0f - 1e-6f);
        sb = fmaxf(sb, 1e-10f);
        const float sb2  = sb * L2E;
        const float kb2  = 256.0f * (sb * sb) * L2E;
        const float cofs = kb2 + 40.0f;   // softmax-invariant shift

        float gv[8];
        gv[0] = ga.x * n0.x;  gv[1] = ga.y * n0.y;
        gv[2] = ga.z * n0.z;  gv[3] = ga.w * n0.w;
        gv[4] = gb.x * n1.x;  gv[5] = gb.y * n1.y;
        gv[6] = gb.z * n1.z;  gv[7] = gb.w * n1.w;

        // Lane-local pass (overlaps the scan)
        float f[8];
        float run = 0.0f;
        float m = -3.4e38f;
        #pragma unroll
        for (int i = 0; i < 8; i++) {
            float bias = (kbase + i == x) ? kb2 : 0.0f;
            float ti = fmaf(sb2, gv[i] + run, bias);
            run = fmaf(rt[i], gv[i], run);
            f[i] = ti;
            m = fmaxf(m, ti);
        }

        // Warp inclusive scan of lane totals
        float inc = run;
        #pragma unroll
        for (int d = 1; d < 32; d <<= 1) {
            float nb = __shfl_up_sync(0xFFFFFFFFu, inc, d);
            if (lane >= d) inc += nb;
        }
        const float excl = inc - run;

        // Lane-local exp (issues while scan drains)
        float sf = 0.0f;
        #pragma unroll
        for (int i = 0; i < 8; i++) {
            f[i] = ex2f(f[i] - m);   // in (0,1]
            sf += f[i];
        }

        const float wq = ex2f(fmaf(sb2, excl, m - cofs));
        const float s_cur = sf * wq;

        // ---- Deferred epilogue of previous row (overlaps front above) ----
        if (it > 0) {
            float s = ps;
            #pragma unroll
            for (int d = 16; d >= 1; d >>= 1)
                s += __shfl_xor_sync(0xFFFFFFFFu, s, d);
            const float scale = pwq * rcpf(s);
            pop[0] = make_float4(pf[0]*scale, pf[1]*scale, pf[2]*scale, pf[3]*scale);
            pop[1] = make_float4(pf[4]*scale, pf[5]*scale, pf[6]*scale, pf[7]*scale);
        }

        // ---- Rotate pipeline state ----
        #pragma unroll
        for (int i = 0; i < 8; i++) pf[i] = f[i];
        pwq = wq; ps = s_cur; pop = op;

        if (!hn) break;
        tp += stride; dp += stride; np += nstep; op += nstep;
        tv = tv_n; x = x_n; n0 = m0; n1 = m1;
    }

    // Final epilogue
    {
        float s = ps;
        #pragma unroll
        for (int d = 16; d >= 1; d >>= 1)
            s += __shfl_xor_sync(0xFFFFFFFFu, s, d);
        const float scale = pwq * rcpf(s);
        pop[0] = make_float4(pf[0]*scale, pf[1]*scale, pf[2]*scale, pf[3]*scale);
        pop[1] = make_float4(pf[4]*scale, pf[5]*scale, pf[6]*scale, pf[7]*scale);
    }
}

extern "C" void kernel_launch(void* const* d_in, const int* in_sizes, int n_in,
                              void* d_out, int out_size)
{
    const int*    data  = (const int*)d_in[0];
    const float*  t     = (const float*)d_in[1];
    const float4* noise = (const float4*)d_in[2];
    float4*       out   = (float4*)d_out;

    const int nrows = in_sizes[0];   // B*S = 16384
    int blocks = (nrows + WARPS_PER_BLOCK - 1) / WARPS_PER_BLOCK;
    if (blocks > BLOCKS_RESIDENT) blocks = BLOCKS_RESIDENT;
    dbf_kernel<<<blocks, THREADS>>>(data, t, noise, out, nrows);
}

// round 14
// speedup vs baseline: 1.0300x; 1.0300x over previous
#include <cuda_runtime.h>

#define KCLS 256
#define WARPS_PER_BLOCK 8
#define THREADS (WARPS_PER_BLOCK * 32)
#define BLOCKS_RESIDENT 592   // 4 blocks/SM * 148 SMs — best measured config

__device__ __forceinline__ float ex2f(float a) {
    float r; asm("ex2.approx.f32 %0, %1;" : "=f"(r) : "f"(a)); return r;
}
__device__ __forceinline__ float rcpf(float a) {
    float r; asm("rcp.approx.f32 %0, %1;" : "=f"(r) : "f"(a)); return r;
}

__global__ __launch_bounds__(THREADS, 4)
void dbf_kernel(const int* __restrict__ data,
                const float* __restrict__ t,
                const float4* __restrict__ noise,
                float4* __restrict__ out,
                int nrows)
{
    __shared__ __align__(16) float sg[KCLS];
    __shared__ __align__(16) float sr[KCLS];   // r_k = h_k/g_k = T/(a+T)

    const int tid  = threadIdx.x;
    const int lane = tid & 31;
    const int warp = tid >> 5;

    // Closed-form Cholesky of C0 = (K+0.001) I - 11^T:
    //   T_k = a/(k-a), g_k = sqrt(a+T_k), h_k = T_k/g_k, a = K+0.001
    {
        const float ALPHA = 256.001f;
        float kf = (float)tid;
        float T  = ALPHA / (kf - ALPHA);
        float gs = ALPHA + T;
        sg[tid] = sqrtf(gs);
        sr[tid] = T / gs;          // ratio h/g
    }
    __syncthreads();

    const int kbase = lane * 8;

    // g and ratio slices, register-resident for the whole loop
    float4 ga = *(const float4*)&sg[kbase];
    float4 gb = *(const float4*)&sg[kbase + 4];
    float4 ra = *(const float4*)&sr[kbase];
    float4 rb = *(const float4*)&sr[kbase + 4];
    const float rt[8] = {ra.x, ra.y, ra.z, ra.w, rb.x, rb.y, rb.z, rb.w};

    const float L2E = 1.4426950408889634f;
    const int stride = gridDim.x * WARPS_PER_BLOCK;
    const int gw = blockIdx.x * WARPS_PER_BLOCK + warp;
    if (gw >= nrows) return;

    const int niter = (nrows - gw + stride - 1) / stride;

    // Strided pointers — constant bumps per iteration
    const float*  tp = t + gw;
    const int*    dp = data + gw;
    const float4* np = noise + (size_t)gw * (KCLS / 4) + lane * 2;
    float4*       op = out   + (size_t)gw * (KCLS / 4) + lane * 2;
    const size_t  nstep = (size_t)stride * (KCLS / 4);

    // Prime pipeline
    float tv = __ldg(tp);
    int   x  = __ldg(dp);
    float4 n0 = __ldg(np + 0);
    float4 n1 = __ldg(np + 1);

    for (int it = 0; it < niter; it++) {
        // ---- Prefetch next row (constant-stride addresses) ----
        const bool hn = (it + 1 < niter);
        float tv_n; int x_n; float4 m0, m1;
        if (hn) {
            tv_n = __ldg(tp + stride);
            x_n  = __ldg(dp + stride);
            m0   = __ldg(np + nstep + 0);
            m1   = __ldg(np + nstep + 1);
        }

        // ---- Per-row scalars ----
        float sb = fminf(tv, 1.0f - 1e-6f);
        sb = fmaxf(sb, 1e-10f);
        const float sb2 = sb * L2E;                 // sb * log2(e)
        const float kb2 = 256.0f * (sb * sb) * L2E; // K*beta*log2(e)

        // Constant per-lane shift m = 40 + (owner? kb2 : 0): cancels exactly
        // in e_i = f_i * 2^u; chosen only for ex2 range safety.
        //   element bias: (k==x) ? -40 : b_off,  b_off = -40 - (owner? kb2:0)
        //   stitch offset: uofs = (owner? 0 : -kb2);  u = sb2*excl + uofs
        // Underflow at large beta flushes non-x classes to 0 = true value.
        const bool  own   = (lane == (x >> 3));
        const float b_off = own ? (-40.0f - kb2) : -40.0f;
        const float uofs  = own ? 0.0f : -kb2;

        // gv only; h*v reconstructed as r*gv in the running sum
        float gv[8];
        gv[0] = ga.x * n0.x;  gv[1] = ga.y * n0.y;
        gv[2] = ga.z * n0.z;  gv[3] = ga.w * n0.w;
        gv[4] = gb.x * n1.x;  gv[5] = gb.y * n1.y;
        gv[6] = gb.z * n1.z;  gv[7] = gb.w * n1.w;

        // ---- Lane-local pass: ex2 issues per element (no max gate);
        //      MUFU overlaps the FMA chain and the scan below ----
        float f[8];
        float run = 0.0f;
        float sf = 0.0f;
        #pragma unroll
        for (int i = 0; i < 8; i++) {
            float bias = (kbase + i == x) ? -40.0f : b_off;
            f[i] = ex2f(fmaf(sb2, gv[i] + run, bias));
            run = fmaf(rt[i], gv[i], run);
            sf += f[i];
        }

        // ---- Warp inclusive scan of lane totals ----
        float inc = run;
        #pragma unroll
        for (int d = 1; d < 32; d <<= 1) {
            float nb = __shfl_up_sync(0xFFFFFFFFu, inc, d);
            if (lane >= d) inc += nb;
        }
        const float excl = inc - run;

        // ---- Stitch: e_i = f_i * 2^u, u = sb2*excl + uofs ----
        const float wq = ex2f(fmaf(sb2, excl, uofs));
        float s = sf * wq;

        // Warp sum
        #pragma unroll
        for (int d = 16; d >= 1; d >>= 1)
            s += __shfl_xor_sync(0xFFFFFFFFu, s, d);

        const float scale = wq * rcpf(s);
        op[0] = make_float4(f[0]*scale, f[1]*scale, f[2]*scale, f[3]*scale);
        op[1] = make_float4(f[4]*scale, f[5]*scale, f[6]*scale, f[7]*scale);

        // ---- Rotate pipeline (constant pointer bumps) ----
        if (!hn) break;
        tp += stride; dp += stride; np += nstep; op += nstep;
        tv = tv_n; x = x_n; n0 = m0; n1 = m1;
    }
}

extern "C" void kernel_launch(void* const* d_in, const int* in_sizes, int n_in,
                              void* d_out, int out_size)
{
    const int*    data  = (const int*)d_in[0];
    const float*  t     = (const float*)d_in[1];
    const float4* noise = (const float4*)d_in[2];
    float4*       out   = (float4*)d_out;

    const int nrows = in_sizes[0];   // B*S = 16384
    int blocks = (nrows + WARPS_PER_BLOCK - 1) / WARPS_PER_BLOCK;
    if (blocks > BLOCKS_RESIDENT) blocks = BLOCKS_RESIDENT;
    dbf_kernel<<<blocks, THREADS>>>(data, t, noise, out, nrows);
}